// round 6
// baseline (speedup 1.0000x reference)
#include <cuda_runtime.h>
#include <cuda_bf16.h>
#include <math.h>

// ---------------------------------------------------------------------------
// CrossCBR propagation — unified-CSR, fused, float4 pair-of-rows gathers.
// R6: accs buffer replaced by per-row inv-norm scalars; shuffle scans;
// int4 edge reads in count/scatter.
// ---------------------------------------------------------------------------
#define NU 100000
#define NI 200000
#define NB 50000
#define FD 64
#define E_UI 1000000
#define E_UB 500000
#define E_BI 1000000

#define B0 0
#define B1 NU                    // 100000
#define B2 (NU + NI)             // 300000
#define B3 (NU + NI + NU)        // 400000
#define B4 (NU + NI + NU + NB)   // 450000
#define NTOT (B4 + NB)           // 500000
#define NPROP B4
#define E_TOT (2 * E_UI + 2 * E_UB + E_BI)   // 4,000,000

// ---------------------------------------------------------------------------
// Static device scratch.
// ---------------------------------------------------------------------------
__device__ int    g_cnt[NTOT];
__device__ int    g_cur[NTOT];
__device__ int    g_ptr[NTOT + 1];
__device__ int    g_col[E_TOT];
__device__ int    g_bsum[512];
__device__ float4 g_feat1[NPROP * 16];   // layer-1 outputs, all 4 segments
__device__ float  g_inv1 [NPROP];        // layer-1 inverse norms
__device__ float4 g_accI [NI * 16];      // item-level item acc (for BI rowmean)

// ---------------------------------------------------------------------------
// CSR build
// ---------------------------------------------------------------------------
__global__ void k_init() {
    int i = blockIdx.x * blockDim.x + threadIdx.x;
    int stride = gridDim.x * blockDim.x;
    for (; i < NTOT; i += stride) g_cnt[i] = 0;
}

// int4 edge reads: thread handles 4 consecutive edges of one segment.
#define Q_UI (E_UI / 4)
#define Q_UB (E_UB / 4)
#define Q_BI (E_BI / 4)
#define Q_TOT (Q_UI + Q_UB + Q_BI)

__global__ void k_count(const int4* __restrict__ ui_row, const int4* __restrict__ ui_col,
                        const int4* __restrict__ ub_row, const int4* __restrict__ ub_col,
                        const int4* __restrict__ bi_row) {
    int i = blockIdx.x * blockDim.x + threadIdx.x;
    int stride = gridDim.x * blockDim.x;
    for (; i < Q_TOT; i += stride) {
        if (i < Q_UI) {
            int4 r = ui_row[i], c = ui_col[i];
            atomicAdd(&g_cnt[r.x], 1); atomicAdd(&g_cnt[r.y], 1);
            atomicAdd(&g_cnt[r.z], 1); atomicAdd(&g_cnt[r.w], 1);
            atomicAdd(&g_cnt[B1 + c.x], 1); atomicAdd(&g_cnt[B1 + c.y], 1);
            atomicAdd(&g_cnt[B1 + c.z], 1); atomicAdd(&g_cnt[B1 + c.w], 1);
        } else if (i < Q_UI + Q_UB) {
            int e = i - Q_UI;
            int4 r = ub_row[e], c = ub_col[e];
            atomicAdd(&g_cnt[B2 + r.x], 1); atomicAdd(&g_cnt[B2 + r.y], 1);
            atomicAdd(&g_cnt[B2 + r.z], 1); atomicAdd(&g_cnt[B2 + r.w], 1);
            atomicAdd(&g_cnt[B3 + c.x], 1); atomicAdd(&g_cnt[B3 + c.y], 1);
            atomicAdd(&g_cnt[B3 + c.z], 1); atomicAdd(&g_cnt[B3 + c.w], 1);
        } else {
            int e = i - Q_UI - Q_UB;
            int4 r = bi_row[e];
            atomicAdd(&g_cnt[B4 + r.x], 1); atomicAdd(&g_cnt[B4 + r.y], 1);
            atomicAdd(&g_cnt[B4 + r.z], 1); atomicAdd(&g_cnt[B4 + r.w], 1);
        }
    }
}

#define SCAN_T 1024
#define SCAN_NB ((NTOT + SCAN_T - 1) / SCAN_T)   // 489

// Phase 1: per-block total of counts (warp-shuffle reduce, 1 sync)
__global__ void k_scan1() {
    __shared__ int wsum[32];
    int tid = threadIdx.x;
    int lane = tid & 31, wid = tid >> 5;
    int i = blockIdx.x * SCAN_T + tid;
    int v = (i < NTOT) ? g_cnt[i] : 0;
    #pragma unroll
    for (int o = 16; o >= 1; o >>= 1) v += __shfl_xor_sync(0xffffffffu, v, o);
    if (lane == 0) wsum[wid] = v;
    __syncthreads();
    if (wid == 0) {
        int y = wsum[lane];
        #pragma unroll
        for (int o = 16; o >= 1; o >>= 1) y += __shfl_xor_sync(0xffffffffu, y, o);
        if (lane == 0) g_bsum[blockIdx.x] = y;
    }
}

// Phase 2: block offset from bsum prefix + block-local scan (shuffle-based)
__global__ void k_scan2() {
    __shared__ int wsum[32];
    __shared__ int wscan[32];
    __shared__ int s_base;
    int tid = threadIdx.x;
    int lane = tid & 31, wid = tid >> 5;
    int bid = blockIdx.x;

    // ---- block offset = sum of bsum[0..bid) ----
    int part = 0;
    for (int k = tid; k < bid; k += SCAN_T) part += g_bsum[k];
    #pragma unroll
    for (int o = 16; o >= 1; o >>= 1) part += __shfl_xor_sync(0xffffffffu, part, o);
    if (lane == 0) wsum[wid] = part;
    __syncthreads();
    if (wid == 0) {
        int y = wsum[lane];
        #pragma unroll
        for (int o = 16; o >= 1; o >>= 1) y += __shfl_xor_sync(0xffffffffu, y, o);
        if (lane == 0) s_base = y;
    }

    // ---- block-local inclusive scan of counts ----
    int i = bid * SCAN_T + tid;
    int v = (i < NTOT) ? g_cnt[i] : 0;
    int x = v;
    #pragma unroll
    for (int o = 1; o < 32; o <<= 1) {
        int t = __shfl_up_sync(0xffffffffu, x, o);
        if (lane >= o) x += t;
    }
    if (lane == 31) wscan[wid] = x;
    __syncthreads();
    if (wid == 0) {
        int y = wscan[lane];
        #pragma unroll
        for (int o = 1; o < 32; o <<= 1) {
            int t = __shfl_up_sync(0xffffffffu, y, o);
            if (lane >= o) y += t;
        }
        wscan[lane] = y;
    }
    __syncthreads();
    int warpbase = (wid > 0) ? wscan[wid - 1] : 0;
    int excl = s_base + warpbase + x - v;
    if (i < NTOT) { g_ptr[i] = excl; g_cur[i] = excl; }
    if (i == NTOT - 1) g_ptr[NTOT] = E_TOT;
}

__global__ void k_scatter(const int4* __restrict__ ui_row, const int4* __restrict__ ui_col,
                          const int4* __restrict__ ub_row, const int4* __restrict__ ub_col,
                          const int4* __restrict__ bi_row, const int4* __restrict__ bi_col) {
    int i = blockIdx.x * blockDim.x + threadIdx.x;
    int stride = gridDim.x * blockDim.x;
    for (; i < Q_TOT; i += stride) {
        if (i < Q_UI) {
            int4 r = ui_row[i], c = ui_col[i];
            g_col[atomicAdd(&g_cur[r.x], 1)] = c.x;
            g_col[atomicAdd(&g_cur[r.y], 1)] = c.y;
            g_col[atomicAdd(&g_cur[r.z], 1)] = c.z;
            g_col[atomicAdd(&g_cur[r.w], 1)] = c.w;
            g_col[atomicAdd(&g_cur[B1 + c.x], 1)] = r.x;
            g_col[atomicAdd(&g_cur[B1 + c.y], 1)] = r.y;
            g_col[atomicAdd(&g_cur[B1 + c.z], 1)] = r.z;
            g_col[atomicAdd(&g_cur[B1 + c.w], 1)] = r.w;
        } else if (i < Q_UI + Q_UB) {
            int e = i - Q_UI;
            int4 r = ub_row[e], c = ub_col[e];
            g_col[atomicAdd(&g_cur[B2 + r.x], 1)] = c.x;
            g_col[atomicAdd(&g_cur[B2 + r.y], 1)] = c.y;
            g_col[atomicAdd(&g_cur[B2 + r.z], 1)] = c.z;
            g_col[atomicAdd(&g_cur[B2 + r.w], 1)] = c.w;
            g_col[atomicAdd(&g_cur[B3 + c.x], 1)] = r.x;
            g_col[atomicAdd(&g_cur[B3 + c.y], 1)] = r.y;
            g_col[atomicAdd(&g_cur[B3 + c.z], 1)] = r.z;
            g_col[atomicAdd(&g_cur[B3 + c.w], 1)] = r.w;
        } else {
            int e = i - Q_UI - Q_UB;
            int4 r = bi_row[e], c = bi_col[e];
            g_col[atomicAdd(&g_cur[B4 + r.x], 1)] = c.x;
            g_col[atomicAdd(&g_cur[B4 + r.y], 1)] = c.y;
            g_col[atomicAdd(&g_cur[B4 + r.z], 1)] = c.z;
            g_col[atomicAdd(&g_cur[B4 + r.w], 1)] = c.w;
        }
    }
}

// ---------------------------------------------------------------------------
// Pair-of-rows gather: warp handles rows (2w, 2w+1); lanes [0,16) -> row0,
// lanes [16,32) -> row1. Each lane holds one float4 of the 64-float row.
// ---------------------------------------------------------------------------
__device__ __forceinline__ float4 gather_row4(const float4* __restrict__ src,
                                              int beg, int deg, int dmax, int hl) {
    float4 acc = make_float4(0.f, 0.f, 0.f, 0.f);
    const int* __restrict__ cols = g_col;
    for (int jj = 0; jj < dmax; jj += 4) {
        #pragma unroll
        for (int k = 0; k < 4; k++) {
            if (jj + k < deg) {
                int c = cols[beg + jj + k];
                float4 v = src[c * 16 + hl];
                acc.x += v.x; acc.y += v.y; acc.z += v.z; acc.w += v.w;
            }
        }
    }
    return acc;
}

__device__ __forceinline__ float half_inv_norm(const float4& a) {
    float sq = a.x * a.x + a.y * a.y + a.z * a.z + a.w * a.w;
    #pragma unroll
    for (int o = 8; o >= 1; o >>= 1) sq += __shfl_xor_sync(0xffffffffu, sq, o);
    return 1.0f / fmaxf(sqrtf(sq), 1e-12f);
}

// layer1: feat1[r] = gather(src_seg); inv1[r] = 1/max(||feat1[r]||,eps)
__global__ void __launch_bounds__(256)
k_layer1(const float* __restrict__ users, const float* __restrict__ items,
         const float* __restrict__ bundles) {
    int warp = (blockIdx.x * blockDim.x + threadIdx.x) >> 5;
    if (warp >= NPROP / 2) return;
    int lane = threadIdx.x & 31;
    int hl = lane & 15;
    int r = 2 * warp + (lane >> 4);

    int beg = g_ptr[r], deg = g_ptr[r + 1] - beg;
    int dmax = max(deg, __shfl_xor_sync(0xffffffffu, deg, 16));

    const float4* src;
    if (r < B1)      src = (const float4*)items;
    else if (r < B2) src = (const float4*)users;
    else if (r < B3) src = (const float4*)bundles;
    else             src = (const float4*)users;

    float4 s = gather_row4(src, beg, deg, dmax, hl);

    g_feat1[r * 16 + hl] = s;
    float inv = half_inv_norm(s);
    if (hl == 0) g_inv1[r] = inv;
}

// layer2: final = (base[r] + feat1[r]*inv1[r]) + norm(gather(feat1_other_seg))
__global__ void __launch_bounds__(256)
k_layer2(float* __restrict__ out,
         const float* __restrict__ users, const float* __restrict__ items,
         const float* __restrict__ bundles) {
    int warp = (blockIdx.x * blockDim.x + threadIdx.x) >> 5;
    if (warp >= NPROP / 2) return;
    int lane = threadIdx.x & 31;
    int hl = lane & 15;
    int r = 2 * warp + (lane >> 4);

    int beg = g_ptr[r], deg = g_ptr[r + 1] - beg;
    int dmax = max(deg, __shfl_xor_sync(0xffffffffu, deg, 16));

    const float4* src;
    const float4* base;
    if (r < B1)      { src = g_feat1 + B1 * 16; base = (const float4*)users   + r * 16; }
    else if (r < B2) { src = g_feat1;           base = (const float4*)items   + (r - B1) * 16; }
    else if (r < B3) { src = g_feat1 + B3 * 16; base = (const float4*)users   + (r - B2) * 16; }
    else             { src = g_feat1 + B2 * 16; base = (const float4*)bundles + (r - B3) * 16; }

    // reconstruct accs[r] = base + feat1*inv1  (bitwise same as R5's staging)
    float4 b0 = base[hl];
    float4 f1 = g_feat1[r * 16 + hl];
    float inv1 = g_inv1[r];
    float4 a0 = make_float4(b0.x + f1.x * inv1, b0.y + f1.y * inv1,
                            b0.z + f1.z * inv1, b0.w + f1.w * inv1);

    float4 s = gather_row4(src, beg, deg, dmax, hl);

    float inv = half_inv_norm(s);
    float4 v = make_float4(a0.x + s.x * inv, a0.y + s.y * inv,
                           a0.z + s.z * inv, a0.w + s.w * inv);

    float4* out4 = (float4*)out;  // out rows are 128 floats = 32 float4
    if (r < B1)      out4[r * 32 + hl] = v;                     // users [0:64)
    else if (r < B2) g_accI[(r - B1) * 16 + hl] = v;            // item acc
    else if (r < B3) out4[(r - B2) * 32 + 16 + hl] = v;         // users [64:128)
    else             out4[(NU + r - B3) * 32 + 16 + hl] = v;    // bundles [64:128)
}

// rowmean: out[bundle, 0:64) = (1/(deg+1e-8)) * sum accI[i]
__global__ void __launch_bounds__(256)
k_rowmean(float* __restrict__ out) {
    int warp = (blockIdx.x * blockDim.x + threadIdx.x) >> 5;
    if (warp >= NB / 2) return;
    int lane = threadIdx.x & 31;
    int hl = lane & 15;
    int b = 2 * warp + (lane >> 4);
    int r = B4 + b;

    int beg = g_ptr[r], deg = g_ptr[r + 1] - beg;
    int dmax = max(deg, __shfl_xor_sync(0xffffffffu, deg, 16));

    float4 s = gather_row4(g_accI, beg, deg, dmax, hl);

    float inv = 1.0f / ((float)deg + 1e-8f);
    ((float4*)out)[(NU + b) * 32 + hl] =
        make_float4(s.x * inv, s.y * inv, s.z * inv, s.w * inv);
}

// ---------------------------------------------------------------------------
// Host launch sequence (graph-capturable, 8 launches)
// ---------------------------------------------------------------------------
extern "C" void kernel_launch(void* const* d_in, const int* in_sizes, int n_in,
                              void* d_out, int out_size) {
    const float* users   = (const float*)d_in[0];
    const float* items   = (const float*)d_in[1];
    const float* bundles = (const float*)d_in[2];
    const int4* ui_row = (const int4*)d_in[3];
    const int4* ui_col = (const int4*)d_in[4];
    const int4* ub_row = (const int4*)d_in[5];
    const int4* ub_col = (const int4*)d_in[6];
    const int4* bi_row = (const int4*)d_in[7];
    const int4* bi_col = (const int4*)d_in[8];
    // d_in[9] = num_layers (constant 2; unrolled)
    float* out = (float*)d_out;

    const int T = 256;
    const int GEDGE = 1024;   // grid-stride over Q_TOT = 625000 quads

    // ---- CSR build ----
    k_init<<<512, T>>>();
    k_count<<<GEDGE, T>>>(ui_row, ui_col, ub_row, ub_col, bi_row);
    k_scan1<<<SCAN_NB, SCAN_T>>>();
    k_scan2<<<SCAN_NB, SCAN_T>>>();
    k_scatter<<<GEDGE, T>>>(ui_row, ui_col, ub_row, ub_col, bi_row, bi_col);

    // ---- propagation: 8 warps = 16 rows per 256-thread block ----
    const int GP = (NPROP / 2 + 7) / 8;
    k_layer1<<<GP, T>>>(users, items, bundles);
    k_layer2<<<GP, T>>>(out, users, items, bundles);

    // ---- bundle item-level rep ----
    k_rowmean<<<(NB / 2 + 7) / 8, T>>>(out);
}

// round 7
// speedup vs baseline: 1.1905x; 1.1905x over previous
#include <cuda_runtime.h>
#include <cuda_fp16.h>
#include <math.h>

// ---------------------------------------------------------------------------
// CrossCBR propagation — unified-CSR, fp16 gathered data, fp32 accumulation.
// Warp handles 4 rows; 8 lanes per row; lane reads uint4 = 8 halves (16B).
// ---------------------------------------------------------------------------
#define NU 100000
#define NI 200000
#define NB 50000
#define FD 64
#define E_UI 1000000
#define E_UB 500000
#define E_BI 1000000

#define B0 0
#define B1 NU                    // 100000  (all boundaries divisible by 4)
#define B2 (NU + NI)             // 300000
#define B3 (NU + NI + NU)        // 400000
#define B4 (NU + NI + NU + NB)   // 450000
#define NTOT (B4 + NB)           // 500000
#define NPROP B4
#define E_TOT (2 * E_UI + 2 * E_UB + E_BI)   // 4,000,000

// ---------------------------------------------------------------------------
// Static device scratch.
// ---------------------------------------------------------------------------
__device__ int    g_cnt[NTOT];
__device__ int    g_cur[NTOT];
__device__ int    g_ptr[NTOT + 1];
__device__ int    g_col[E_TOT];
__device__ int    g_bsum[512];
__device__ float  g_inv1[NPROP];          // layer-1 inverse norms (fp32)
__device__ uint4  g_hu[NU * 8];           // users   fp16 (8 halves per uint4)
__device__ uint4  g_hi[NI * 8];           // items   fp16
__device__ uint4  g_hb[NB * 8];           // bundles fp16
__device__ uint4  g_f1h[NPROP * 8];       // layer-1 outputs fp16
__device__ uint4  g_aIh[NI * 8];          // item-level item acc fp16

// ---------------------------------------------------------------------------
// fp16 helpers
// ---------------------------------------------------------------------------
__device__ __forceinline__ unsigned f2h(float x, float y) {
    __half2 h = __floats2half2_rn(x, y);
    return *reinterpret_cast<unsigned*>(&h);
}
__device__ __forceinline__ float2 h2f(unsigned u) {
    __half2 h = *reinterpret_cast<__half2*>(&u);
    return __half22float2(h);
}
__device__ __forceinline__ uint4 pack8(const float4* __restrict__ s, int i) {
    float4 a = s[2 * i], b = s[2 * i + 1];
    uint4 u;
    u.x = f2h(a.x, a.y); u.y = f2h(a.z, a.w);
    u.z = f2h(b.x, b.y); u.w = f2h(b.z, b.w);
    return u;
}

// ---------------------------------------------------------------------------
// CSR build + fused fp16 conversion
// ---------------------------------------------------------------------------
__global__ void k_init() {
    int i = blockIdx.x * blockDim.x + threadIdx.x;
    int stride = gridDim.x * blockDim.x;
    for (; i < NTOT; i += stride) g_cnt[i] = 0;
}

#define Q_UI (E_UI / 4)
#define Q_UB (E_UB / 4)
#define Q_BI (E_BI / 4)
#define Q_TOT (Q_UI + Q_UB + Q_BI)          // 625000
#define CVT_U (NU * 8)                      // uint4 packs per array
#define CVT_I (NI * 8)
#define CVT_B (NB * 8)
#define WORK_TOT (Q_TOT + CVT_U + CVT_I + CVT_B)   // 625000 + 2800000

__global__ void k_count_cvt(const int4* __restrict__ ui_row, const int4* __restrict__ ui_col,
                            const int4* __restrict__ ub_row, const int4* __restrict__ ub_col,
                            const int4* __restrict__ bi_row,
                            const float4* __restrict__ users, const float4* __restrict__ items,
                            const float4* __restrict__ bundles) {
    int i = blockIdx.x * blockDim.x + threadIdx.x;
    int stride = gridDim.x * blockDim.x;
    for (; i < WORK_TOT; i += stride) {
        if (i < Q_UI) {
            int4 r = ui_row[i], c = ui_col[i];
            atomicAdd(&g_cnt[r.x], 1); atomicAdd(&g_cnt[r.y], 1);
            atomicAdd(&g_cnt[r.z], 1); atomicAdd(&g_cnt[r.w], 1);
            atomicAdd(&g_cnt[B1 + c.x], 1); atomicAdd(&g_cnt[B1 + c.y], 1);
            atomicAdd(&g_cnt[B1 + c.z], 1); atomicAdd(&g_cnt[B1 + c.w], 1);
        } else if (i < Q_UI + Q_UB) {
            int e = i - Q_UI;
            int4 r = ub_row[e], c = ub_col[e];
            atomicAdd(&g_cnt[B2 + r.x], 1); atomicAdd(&g_cnt[B2 + r.y], 1);
            atomicAdd(&g_cnt[B2 + r.z], 1); atomicAdd(&g_cnt[B2 + r.w], 1);
            atomicAdd(&g_cnt[B3 + c.x], 1); atomicAdd(&g_cnt[B3 + c.y], 1);
            atomicAdd(&g_cnt[B3 + c.z], 1); atomicAdd(&g_cnt[B3 + c.w], 1);
        } else if (i < Q_TOT) {
            int e = i - Q_UI - Q_UB;
            int4 r = bi_row[e];
            atomicAdd(&g_cnt[B4 + r.x], 1); atomicAdd(&g_cnt[B4 + r.y], 1);
            atomicAdd(&g_cnt[B4 + r.z], 1); atomicAdd(&g_cnt[B4 + r.w], 1);
        } else {
            int j = i - Q_TOT;
            if (j < CVT_U)               g_hu[j] = pack8(users, j);
            else if (j < CVT_U + CVT_I)  g_hi[j - CVT_U] = pack8(items, j - CVT_U);
            else                         g_hb[j - CVT_U - CVT_I] = pack8(bundles, j - CVT_U - CVT_I);
        }
    }
}

#define SCAN_T 1024
#define SCAN_NB ((NTOT + SCAN_T - 1) / SCAN_T)   // 489

__global__ void k_scan1() {
    __shared__ int wsum[32];
    int tid = threadIdx.x;
    int lane = tid & 31, wid = tid >> 5;
    int i = blockIdx.x * SCAN_T + tid;
    int v = (i < NTOT) ? g_cnt[i] : 0;
    #pragma unroll
    for (int o = 16; o >= 1; o >>= 1) v += __shfl_xor_sync(0xffffffffu, v, o);
    if (lane == 0) wsum[wid] = v;
    __syncthreads();
    if (wid == 0) {
        int y = wsum[lane];
        #pragma unroll
        for (int o = 16; o >= 1; o >>= 1) y += __shfl_xor_sync(0xffffffffu, y, o);
        if (lane == 0) g_bsum[blockIdx.x] = y;
    }
}

__global__ void k_scan2() {
    __shared__ int wsum[32];
    __shared__ int wscan[32];
    __shared__ int s_base;
    int tid = threadIdx.x;
    int lane = tid & 31, wid = tid >> 5;
    int bid = blockIdx.x;

    int part = 0;
    for (int k = tid; k < bid; k += SCAN_T) part += g_bsum[k];
    #pragma unroll
    for (int o = 16; o >= 1; o >>= 1) part += __shfl_xor_sync(0xffffffffu, part, o);
    if (lane == 0) wsum[wid] = part;
    __syncthreads();
    if (wid == 0) {
        int y = wsum[lane];
        #pragma unroll
        for (int o = 16; o >= 1; o >>= 1) y += __shfl_xor_sync(0xffffffffu, y, o);
        if (lane == 0) s_base = y;
    }

    int i = bid * SCAN_T + tid;
    int v = (i < NTOT) ? g_cnt[i] : 0;
    int x = v;
    #pragma unroll
    for (int o = 1; o < 32; o <<= 1) {
        int t = __shfl_up_sync(0xffffffffu, x, o);
        if (lane >= o) x += t;
    }
    if (lane == 31) wscan[wid] = x;
    __syncthreads();
    if (wid == 0) {
        int y = wscan[lane];
        #pragma unroll
        for (int o = 1; o < 32; o <<= 1) {
            int t = __shfl_up_sync(0xffffffffu, y, o);
            if (lane >= o) y += t;
        }
        wscan[lane] = y;
    }
    __syncthreads();
    int warpbase = (wid > 0) ? wscan[wid - 1] : 0;
    int excl = s_base + warpbase + x - v;
    if (i < NTOT) { g_ptr[i] = excl; g_cur[i] = excl; }
    if (i == NTOT - 1) g_ptr[NTOT] = E_TOT;
}

__global__ void k_scatter(const int4* __restrict__ ui_row, const int4* __restrict__ ui_col,
                          const int4* __restrict__ ub_row, const int4* __restrict__ ub_col,
                          const int4* __restrict__ bi_row, const int4* __restrict__ bi_col) {
    int i = blockIdx.x * blockDim.x + threadIdx.x;
    int stride = gridDim.x * blockDim.x;
    for (; i < Q_TOT; i += stride) {
        if (i < Q_UI) {
            int4 r = ui_row[i], c = ui_col[i];
            g_col[atomicAdd(&g_cur[r.x], 1)] = c.x;
            g_col[atomicAdd(&g_cur[r.y], 1)] = c.y;
            g_col[atomicAdd(&g_cur[r.z], 1)] = c.z;
            g_col[atomicAdd(&g_cur[r.w], 1)] = c.w;
            g_col[atomicAdd(&g_cur[B1 + c.x], 1)] = r.x;
            g_col[atomicAdd(&g_cur[B1 + c.y], 1)] = r.y;
            g_col[atomicAdd(&g_cur[B1 + c.z], 1)] = r.z;
            g_col[atomicAdd(&g_cur[B1 + c.w], 1)] = r.w;
        } else if (i < Q_UI + Q_UB) {
            int e = i - Q_UI;
            int4 r = ub_row[e], c = ub_col[e];
            g_col[atomicAdd(&g_cur[B2 + r.x], 1)] = c.x;
            g_col[atomicAdd(&g_cur[B2 + r.y], 1)] = c.y;
            g_col[atomicAdd(&g_cur[B2 + r.z], 1)] = c.z;
            g_col[atomicAdd(&g_cur[B2 + r.w], 1)] = c.w;
            g_col[atomicAdd(&g_cur[B3 + c.x], 1)] = r.x;
            g_col[atomicAdd(&g_cur[B3 + c.y], 1)] = r.y;
            g_col[atomicAdd(&g_cur[B3 + c.z], 1)] = r.z;
            g_col[atomicAdd(&g_cur[B3 + c.w], 1)] = r.w;
        } else {
            int e = i - Q_UI - Q_UB;
            int4 r = bi_row[e], c = bi_col[e];
            g_col[atomicAdd(&g_cur[B4 + r.x], 1)] = c.x;
            g_col[atomicAdd(&g_cur[B4 + r.y], 1)] = c.y;
            g_col[atomicAdd(&g_cur[B4 + r.z], 1)] = c.z;
            g_col[atomicAdd(&g_cur[B4 + r.w], 1)] = c.w;
        }
    }
}

// ---------------------------------------------------------------------------
// fp16 gather: warp handles rows (4w..4w+3); lane group of 8 per row.
// Each lane reads uint4 = 8 halves (16B) of the 128B row; fp32 accumulate.
// ---------------------------------------------------------------------------
__device__ __forceinline__ void gather_row_h(const uint4* __restrict__ src,
                                             int beg, int deg, int dmax, int hl,
                                             float2 acc[4]) {
    const int* __restrict__ cols = g_col;
    for (int jj = 0; jj < dmax; jj += 4) {
        #pragma unroll
        for (int k = 0; k < 4; k++) {
            if (jj + k < deg) {
                int c = cols[beg + jj + k];
                uint4 v = src[c * 8 + hl];
                float2 f0 = h2f(v.x), f1 = h2f(v.y), f2 = h2f(v.z), f3 = h2f(v.w);
                acc[0].x += f0.x; acc[0].y += f0.y;
                acc[1].x += f1.x; acc[1].y += f1.y;
                acc[2].x += f2.x; acc[2].y += f2.y;
                acc[3].x += f3.x; acc[3].y += f3.y;
            }
        }
    }
}

// L2 norm over one row (8-lane group): reduce local sq over xor 1,2,4.
__device__ __forceinline__ float row_inv_norm(const float2 a[4]) {
    float sq = a[0].x * a[0].x + a[0].y * a[0].y + a[1].x * a[1].x + a[1].y * a[1].y
             + a[2].x * a[2].x + a[2].y * a[2].y + a[3].x * a[3].x + a[3].y * a[3].y;
    #pragma unroll
    for (int o = 4; o >= 1; o >>= 1) sq += __shfl_xor_sync(0xffffffffu, sq, o);
    return 1.0f / fmaxf(sqrtf(sq), 1e-12f);
}

__device__ __forceinline__ int row_dmax(int deg) {
    int d = max(deg, __shfl_xor_sync(0xffffffffu, deg, 8));
    return max(d, __shfl_xor_sync(0xffffffffu, d, 16));
}

// layer1: feat1[r] = gather(src_seg) -> fp16; inv1[r] = 1/max(||feat1[r]||,eps)
__global__ void __launch_bounds__(256)
k_layer1() {
    int warp = (blockIdx.x * blockDim.x + threadIdx.x) >> 5;
    if (warp >= NPROP / 4) return;
    int lane = threadIdx.x & 31;
    int hl = lane & 7;
    int r = 4 * warp + (lane >> 3);

    int beg = g_ptr[r], deg = g_ptr[r + 1] - beg;
    int dmax = row_dmax(deg);

    const uint4* src;
    if (r < B1)      src = g_hi;
    else if (r < B2) src = g_hu;
    else if (r < B3) src = g_hb;
    else             src = g_hu;

    float2 acc[4] = { {0.f,0.f},{0.f,0.f},{0.f,0.f},{0.f,0.f} };
    gather_row_h(src, beg, deg, dmax, hl, acc);

    uint4 p;
    p.x = f2h(acc[0].x, acc[0].y); p.y = f2h(acc[1].x, acc[1].y);
    p.z = f2h(acc[2].x, acc[2].y); p.w = f2h(acc[3].x, acc[3].y);
    g_f1h[r * 8 + hl] = p;

    float inv = row_inv_norm(acc);
    if (hl == 0) g_inv1[r] = inv;
}

// layer2: final = (base + feat1*inv1) + norm(gather(feat1_other_seg))
__global__ void __launch_bounds__(256)
k_layer2(float* __restrict__ out) {
    int warp = (blockIdx.x * blockDim.x + threadIdx.x) >> 5;
    if (warp >= NPROP / 4) return;
    int lane = threadIdx.x & 31;
    int hl = lane & 7;
    int r = 4 * warp + (lane >> 3);

    int beg = g_ptr[r], deg = g_ptr[r + 1] - beg;
    int dmax = row_dmax(deg);

    const uint4* src;
    const uint4* base;
    if (r < B1)      { src = g_f1h + B1 * 8; base = g_hu + r * 8; }
    else if (r < B2) { src = g_f1h;          base = g_hi + (r - B1) * 8; }
    else if (r < B3) { src = g_f1h + B3 * 8; base = g_hu + (r - B2) * 8; }
    else             { src = g_f1h + B2 * 8; base = g_hb + (r - B3) * 8; }

    // a0 = base + feat1 * inv1
    uint4 bh = base[hl];
    uint4 fh = g_f1h[r * 8 + hl];
    float inv1 = g_inv1[r];
    float2 a0[4];
    {
        float2 b0 = h2f(bh.x), b1 = h2f(bh.y), b2 = h2f(bh.z), b3 = h2f(bh.w);
        float2 f0 = h2f(fh.x), f1 = h2f(fh.y), f2 = h2f(fh.z), f3 = h2f(fh.w);
        a0[0] = make_float2(b0.x + f0.x * inv1, b0.y + f0.y * inv1);
        a0[1] = make_float2(b1.x + f1.x * inv1, b1.y + f1.y * inv1);
        a0[2] = make_float2(b2.x + f2.x * inv1, b2.y + f2.y * inv1);
        a0[3] = make_float2(b3.x + f3.x * inv1, b3.y + f3.y * inv1);
    }

    float2 acc[4] = { {0.f,0.f},{0.f,0.f},{0.f,0.f},{0.f,0.f} };
    gather_row_h(src, beg, deg, dmax, hl, acc);

    float inv = row_inv_norm(acc);
    float2 v[4];
    #pragma unroll
    for (int q = 0; q < 4; q++)
        v[q] = make_float2(a0[q].x + acc[q].x * inv, a0[q].y + acc[q].y * inv);

    if (r >= B1 && r < B2) {
        // item acc -> fp16 for rowmean gather
        uint4 p;
        p.x = f2h(v[0].x, v[0].y); p.y = f2h(v[1].x, v[1].y);
        p.z = f2h(v[2].x, v[2].y); p.w = f2h(v[3].x, v[3].y);
        g_aIh[(r - B1) * 8 + hl] = p;
    } else {
        float4 o0 = make_float4(v[0].x, v[0].y, v[1].x, v[1].y);
        float4 o1 = make_float4(v[2].x, v[2].y, v[3].x, v[3].y);
        float4* out4 = (float4*)out;   // out rows = 128 floats = 32 float4
        int slot;
        if (r < B1)      slot = r * 32 + hl * 2;                    // users [0:64)
        else if (r < B3) slot = (r - B2) * 32 + 16 + hl * 2;        // users [64:128)
        else             slot = (NU + r - B3) * 32 + 16 + hl * 2;   // bundles [64:128)
        out4[slot] = o0;
        out4[slot + 1] = o1;
    }
}

// rowmean: out[bundle, 0:64) = (1/(deg+1e-8)) * sum accI[i]
__global__ void __launch_bounds__(256)
k_rowmean(float* __restrict__ out) {
    int warp = (blockIdx.x * blockDim.x + threadIdx.x) >> 5;
    if (warp >= NB / 4) return;
    int lane = threadIdx.x & 31;
    int hl = lane & 7;
    int b = 4 * warp + (lane >> 3);
    int r = B4 + b;

    int beg = g_ptr[r], deg = g_ptr[r + 1] - beg;
    int dmax = row_dmax(deg);

    float2 acc[4] = { {0.f,0.f},{0.f,0.f},{0.f,0.f},{0.f,0.f} };
    gather_row_h(g_aIh, beg, deg, dmax, hl, acc);

    float inv = 1.0f / ((float)deg + 1e-8f);
    float4 o0 = make_float4(acc[0].x * inv, acc[0].y * inv, acc[1].x * inv, acc[1].y * inv);
    float4 o1 = make_float4(acc[2].x * inv, acc[2].y * inv, acc[3].x * inv, acc[3].y * inv);
    float4* out4 = (float4*)out;
    int slot = (NU + b) * 32 + hl * 2;
    out4[slot] = o0;
    out4[slot + 1] = o1;
}

// ---------------------------------------------------------------------------
// Host launch sequence (graph-capturable, 8 launches)
// ---------------------------------------------------------------------------
extern "C" void kernel_launch(void* const* d_in, const int* in_sizes, int n_in,
                              void* d_out, int out_size) {
    const float4* users   = (const float4*)d_in[0];
    const float4* items   = (const float4*)d_in[1];
    const float4* bundles = (const float4*)d_in[2];
    const int4* ui_row = (const int4*)d_in[3];
    const int4* ui_col = (const int4*)d_in[4];
    const int4* ub_row = (const int4*)d_in[5];
    const int4* ub_col = (const int4*)d_in[6];
    const int4* bi_row = (const int4*)d_in[7];
    const int4* bi_col = (const int4*)d_in[8];
    // d_in[9] = num_layers (constant 2; unrolled)
    float* out = (float*)d_out;

    const int T = 256;

    // ---- CSR build + fp16 conversion ----
    k_init<<<512, T>>>();
    k_count_cvt<<<2048, T>>>(ui_row, ui_col, ub_row, ub_col, bi_row,
                             users, items, bundles);
    k_scan1<<<SCAN_NB, SCAN_T>>>();
    k_scan2<<<SCAN_NB, SCAN_T>>>();
    k_scatter<<<1024, T>>>(ui_row, ui_col, ub_row, ub_col, bi_row, bi_col);

    // ---- propagation: 8 warps = 32 rows per 256-thread block ----
    const int GP = (NPROP / 4 + 7) / 8;
    k_layer1<<<GP, T>>>();
    k_layer2<<<GP, T>>>(out);

    // ---- bundle item-level rep ----
    k_rowmean<<<(NB / 4 + 7) / 8, T>>>(out);
}